// round 1
// baseline (speedup 1.0000x reference)
#include <cuda_runtime.h>
#include <cuda_bf16.h>
#include <math.h>

#define NN 512
#define BB 64
#define NZ 128            // B*2 branch instances
#define H1 128
#define H2 64
#define H3 32
#define OUTD 8
#define CLS 16
#define PDIM 72           // OUT*OUT + OUT
#define CDIM 48           // H3 + CLS

// ---------------- scratch (single static device buffer, no allocs) ----------
// layout (floats):
//   d   : NZ*NN                       = 65,536
//   H1b : NZ*NN*H1                    = 8,388,608
//   H2b : NZ*NN*H2                    = 4,194,304
//   H3b : NZ*NN*H3                    = 2,097,152
//   H4b : NZ*NN*OUTD                  = 524,288
//   Zb  : NZ*NN*H2 (max of Z2/Z3/Z4)  = 4,194,304
//   WBb : NZ*PDIM                     = 9,216
//   CCb : BB*2*NN*OUTD                = 524,288
static const size_t OFF_D   = 0;
static const size_t OFF_H1  = OFF_D   + (size_t)NZ*NN;
static const size_t OFF_H2  = OFF_H1  + (size_t)NZ*NN*H1;
static const size_t OFF_H3  = OFF_H2  + (size_t)NZ*NN*H2;
static const size_t OFF_H4  = OFF_H3  + (size_t)NZ*NN*H3;
static const size_t OFF_Z   = OFF_H4  + (size_t)NZ*NN*OUTD;
static const size_t OFF_WB  = OFF_Z   + (size_t)NZ*NN*H2;
static const size_t OFF_CC  = OFF_WB  + (size_t)NZ*PDIM;
static const size_t TOTAL_SCRATCH = OFF_CC + (size_t)BB*2*NN*OUTD;

__device__ float g_scratch[TOTAL_SCRATCH];

// ---------------- kernel 1: row-sum normalization factors -------------------
// d[z, i] = rsqrt(1 + sum_j adj[b2, i, j]),  z = s*64 + b, b2 = b*2 + s
__global__ void rowsum_kernel(const float* __restrict__ adj, float* __restrict__ dout) {
    int gw   = (blockIdx.x * blockDim.x + threadIdx.x) >> 5;  // global warp = row id
    int lane = threadIdx.x & 31;
    int b2  = gw >> 9;          // 0..127  (b*2+s)
    int row = gw & 511;
    const float* r = adj + (size_t)b2 * NN * NN + (size_t)row * NN;
    float ssum = 0.f;
    #pragma unroll
    for (int k = lane; k < NN; k += 32) ssum += r[k];
    #pragma unroll
    for (int o = 16; o; o >>= 1) ssum += __shfl_xor_sync(0xffffffffu, ssum, o);
    if (lane == 0) {
        int s = b2 & 1, b = b2 >> 1;
        dout[(size_t)(s * BB + b) * NN + row] = rsqrtf(ssum + 1.0f);
    }
}

// ---------------- generic register-tiled SGEMM (plain): C = A @ W -----------
template<int BM, int BN, int BK, int TM, int TN>
__global__ void gemm_plain_kernel(const float* __restrict__ A,
                                  const float* __restrict__ W,
                                  float* __restrict__ C,
                                  int K, int Ncols) {
    __shared__ float As[BK][BM + 1];
    __shared__ float Bs[BK][BN + 1];
    const int NT  = (BM / TM) * (BN / TN);
    const int tx  = threadIdx.x, ty = threadIdx.y;
    const int tid = ty * (BN / TN) + tx;
    const int m0  = blockIdx.x * BM;
    const int n0  = blockIdx.y * BN;
    float acc[TM][TN] = {};
    for (int k0 = 0; k0 < K; k0 += BK) {
        #pragma unroll
        for (int idx = tid; idx < BM * BK; idx += NT) {
            int k = idx % BK, m = idx / BK;
            As[k][m] = A[(size_t)(m0 + m) * K + k0 + k];
        }
        #pragma unroll
        for (int idx = tid; idx < BK * BN; idx += NT) {
            int n = idx % BN, k = idx / BN;
            Bs[k][n] = W[(size_t)(k0 + k) * Ncols + n0 + n];
        }
        __syncthreads();
        #pragma unroll
        for (int kk = 0; kk < BK; kk++) {
            float a[TM], b[TN];
            #pragma unroll
            for (int m = 0; m < TM; m++) a[m] = As[kk][ty * TM + m];
            #pragma unroll
            for (int n = 0; n < TN; n++) b[n] = Bs[kk][tx * TN + n];
            #pragma unroll
            for (int m = 0; m < TM; m++)
                #pragma unroll
                for (int n = 0; n < TN; n++) acc[m][n] += a[m] * b[n];
        }
        __syncthreads();
    }
    #pragma unroll
    for (int m = 0; m < TM; m++) {
        int i = m0 + ty * TM + m;
        #pragma unroll
        for (int n = 0; n < TN; n++) {
            int c = n0 + tx * TN + n;
            C[(size_t)i * Ncols + c] = acc[m][n];
        }
    }
}

// ---------------- GCN layer: H = act(d_i*(adj@(d∘Z)) + d_i^2*Z_i + bias) ----
// adjbase pre-offset by s (per-block stride 2*N*N); Zbase/dbase/Hbase pre-offset by s.
template<int BM, int BN, int BK, int TM, int TN, bool ACT, bool ZSHARED>
__global__ void gcn_layer_kernel(const float* __restrict__ adjbase,
                                 const float* __restrict__ Zbase,
                                 const float* __restrict__ dbase,
                                 const float* __restrict__ bias,
                                 float* __restrict__ Hbase,
                                 int Ncols) {
    const int b = blockIdx.z;
    const float* A  = adjbase + (size_t)b * (2 * NN * NN);
    const float* Zb = ZSHARED ? Zbase : Zbase + (size_t)b * NN * Ncols;
    const float* dz = dbase + (size_t)b * NN;
    float* Hout     = Hbase + (size_t)b * NN * Ncols;

    __shared__ float As[BK][BM + 1];
    __shared__ float Bs[BK][BN + 1];
    const int NT  = (BM / TM) * (BN / TN);
    const int tx  = threadIdx.x, ty = threadIdx.y;
    const int tid = ty * (BN / TN) + tx;
    const int m0  = blockIdx.x * BM;
    const int n0  = blockIdx.y * BN;
    float acc[TM][TN] = {};
    for (int k0 = 0; k0 < NN; k0 += BK) {
        #pragma unroll
        for (int idx = tid; idx < BM * BK; idx += NT) {
            int k = idx % BK, m = idx / BK;
            As[k][m] = A[(size_t)(m0 + m) * NN + k0 + k];
        }
        #pragma unroll
        for (int idx = tid; idx < BK * BN; idx += NT) {
            int n = idx % BN, k = idx / BN;
            Bs[k][n] = Zb[(size_t)(k0 + k) * Ncols + n0 + n] * dz[k0 + k];
        }
        __syncthreads();
        #pragma unroll
        for (int kk = 0; kk < BK; kk++) {
            float a[TM], bf[TN];
            #pragma unroll
            for (int m = 0; m < TM; m++) a[m] = As[kk][ty * TM + m];
            #pragma unroll
            for (int n = 0; n < TN; n++) bf[n] = Bs[kk][tx * TN + n];
            #pragma unroll
            for (int m = 0; m < TM; m++)
                #pragma unroll
                for (int n = 0; n < TN; n++) acc[m][n] += a[m] * bf[n];
        }
        __syncthreads();
    }
    #pragma unroll
    for (int m = 0; m < TM; m++) {
        int i = m0 + ty * TM + m;
        float di = dz[i];
        #pragma unroll
        for (int n = 0; n < TN; n++) {
            int c = n0 + tx * TN + n;
            float zv = Zb[(size_t)i * Ncols + c];
            float v = di * acc[m][n] + di * di * zv + bias[c];
            if (ACT) v = (v >= 0.f) ? v : 0.2f * v;
            Hout[(size_t)i * Ncols + c] = v;
        }
    }
}

// ---------------- dynamic head params: per z compute w(8x8)+b(8) ------------
__global__ void dcl_params_kernel(const int* __restrict__ task,
                                  const float* __restrict__ wc,
                                  const float* __restrict__ H3b,
                                  float* __restrict__ wb) {
    int z = blockIdx.x;             // z = s*64 + b
    int b = z & 63;
    const float* conv3 = H3b + (size_t)z * NN * H3;
    __shared__ float partial[256];
    __shared__ float xc[CDIM];
    int tid = threadIdx.x;
    int col = tid & 31, g = tid >> 5;
    float p = 0.f;
    for (int r = g; r < NN; r += 8) p += conv3[(size_t)r * H3 + col];
    partial[tid] = p;
    __syncthreads();
    if (tid < H3) {
        float sum = 0.f;
        #pragma unroll
        for (int gg = 0; gg < 8; gg++) sum += partial[gg * 32 + tid];
        xc[tid] = sum * (1.0f / (float)NN);
    }
    if (tid >= H3 && tid < CDIM) {
        xc[tid] = (task[b] == tid - H3) ? 1.f : 0.f;
    }
    __syncthreads();
    if (tid < PDIM) {
        float acc = 0.f;
        #pragma unroll
        for (int c = 0; c < CDIM; c++) acc += wc[tid * CDIM + c] * xc[c];
        wb[(size_t)z * PDIM + tid] = acc;
    }
}

// ---------------- cc kernel: logits + interleave scatter --------------------
__global__ void cc_kernel(const float* __restrict__ H4b,
                          const float* __restrict__ wb,
                          float* __restrict__ cc) {
    int z = blockIdx.x;            // z = q*64 + b  (q = branch)
    int q = z >> 6, b = z & 63;
    __shared__ float flat[NN * OUTD];   // conv4[b,q] flattened (4096)
    __shared__ float wm[64];
    __shared__ float bv[8];
    int tid = threadIdx.x;
    const float4* src4 = (const float4*)(H4b + (size_t)z * NN * OUTD);
    float4* dst4 = (float4*)flat;
    for (int i = tid; i < NN * OUTD / 4; i += 256) dst4[i] = src4[i];
    if (tid < 64) wm[tid] = wb[(size_t)z * PDIM + tid];
    if (tid < 8)  bv[tid] = wb[(size_t)z * PDIM + 64 + tid];
    __syncthreads();
    for (int f = tid; f < NN * OUTD; f += 256) {
        int r = f >> 9, c = f & 511;         // logits[r, c]
        float v = bv[r];
        #pragma unroll
        for (int i = 0; i < 8; i++) v += wm[r * 8 + i] * flat[i * NN + c];
        int n = f >> 3, o = f & 7;           // L[n, o]
        int scc = n >> 8;
        int n2 = ((n & 255) << 1) | q;
        cc[(((size_t)(b * 2 + scc) * NN + n2) << 3) + o] = v;
    }
}

// ---------------- final: out = softplus(-(cc @ cc^T)) -----------------------
__global__ void final_kernel(const float* __restrict__ cc, float* __restrict__ out) {
    int zz = blockIdx.z;           // b*2 + scc
    __shared__ float Msm[NN * OUTD];
    int tid = threadIdx.y * 16 + threadIdx.x;
    const float4* src = (const float4*)(cc + (size_t)zz * NN * OUTD);
    float4* dst = (float4*)Msm;
    for (int i = tid; i < NN * OUTD / 4; i += 256) dst[i] = src[i];
    __syncthreads();
    int i0 = blockIdx.y * 64 + threadIdx.y * 4;
    int j0 = blockIdx.x * 64 + threadIdx.x * 4;
    float ai[4][8], aj[4][8];
    #pragma unroll
    for (int m = 0; m < 4; m++)
        #pragma unroll
        for (int o = 0; o < 8; o++) ai[m][o] = Msm[(i0 + m) * 8 + o];
    #pragma unroll
    for (int n = 0; n < 4; n++)
        #pragma unroll
        for (int o = 0; o < 8; o++) aj[n][o] = Msm[(j0 + n) * 8 + o];
    float* ob = out + (size_t)zz * NN * NN;
    #pragma unroll
    for (int m = 0; m < 4; m++) {
        float r[4];
        #pragma unroll
        for (int n = 0; n < 4; n++) {
            float x = 0.f;
            #pragma unroll
            for (int o = 0; o < 8; o++) x += ai[m][o] * aj[n][o];
            // softplus(-x) = -log_sigmoid(x)
            r[n] = log1pf(expf(-fabsf(x))) + fmaxf(-x, 0.f);
        }
        *(float4*)(ob + (size_t)(i0 + m) * NN + j0) = make_float4(r[0], r[1], r[2], r[3]);
    }
}

// ---------------- host orchestration ----------------------------------------
extern "C" void kernel_launch(void* const* d_in, const int* in_sizes, int n_in,
                              void* d_out, int out_size) {
    const float* adj  = (const float*)d_in[0];
    const int*   task = (const int*)d_in[1];
    const float* w[2][4];
    const float* bia[2][4];
    int idx = 2;
    for (int s = 0; s < 2; s++)
        for (int l = 0; l < 4; l++) {
            w[s][l]   = (const float*)d_in[idx++];
            bia[s][l] = (const float*)d_in[idx++];
        }
    const float* wc = (const float*)d_in[18];
    float* out = (float*)d_out;

    float* base = nullptr;
    cudaGetSymbolAddress((void**)&base, g_scratch);
    float* p_d  = base + OFF_D;
    float* p_H1 = base + OFF_H1;
    float* p_H2 = base + OFF_H2;
    float* p_H3 = base + OFF_H3;
    float* p_H4 = base + OFF_H4;
    float* p_Z  = base + OFF_Z;
    float* p_WB = base + OFF_WB;
    float* p_CC = base + OFF_CC;

    const size_t DH  = (size_t)BB * NN;          // per-s stride of d
    const size_t S1  = (size_t)BB * NN * H1;     // per-s stride of H1
    const size_t S2  = (size_t)BB * NN * H2;
    const size_t S3  = (size_t)BB * NN * H3;
    const size_t S4  = (size_t)BB * NN * OUTD;

    // 1) degree factors
    rowsum_kernel<<<NZ * NN / 8, 256>>>(adj, p_d);

    // 2) layer 1 (Z = W1, shared across batch)
    for (int s = 0; s < 2; s++) {
        gcn_layer_kernel<64, 64, 32, 4, 4, true, true>
            <<<dim3(8, 2, BB), dim3(16, 16)>>>(
                adj + (size_t)s * NN * NN, w[s][0], p_d + s * DH,
                bia[s][0], p_H1 + s * S1, H1);
    }
    // 3) layer 2
    for (int s = 0; s < 2; s++)
        gemm_plain_kernel<64, 64, 32, 4, 4>
            <<<dim3(BB * NN / 64, 1), dim3(16, 16)>>>(
                p_H1 + s * S1, w[s][1], p_Z + s * S2, H1, H2);
    for (int s = 0; s < 2; s++)
        gcn_layer_kernel<64, 64, 32, 4, 4, true, false>
            <<<dim3(8, 1, BB), dim3(16, 16)>>>(
                adj + (size_t)s * NN * NN, p_Z + s * S2, p_d + s * DH,
                bia[s][1], p_H2 + s * S2, H2);
    // 4) layer 3
    for (int s = 0; s < 2; s++)
        gemm_plain_kernel<64, 32, 32, 4, 4>
            <<<dim3(BB * NN / 64, 1), dim3(8, 16)>>>(
                p_H2 + s * S2, w[s][2], p_Z + s * S3, H2, H3);
    for (int s = 0; s < 2; s++)
        gcn_layer_kernel<64, 32, 32, 4, 4, true, false>
            <<<dim3(8, 1, BB), dim3(8, 16)>>>(
                adj + (size_t)s * NN * NN, p_Z + s * S3, p_d + s * DH,
                bia[s][2], p_H3 + s * S3, H3);
    // 5) layer 4 (no activation) -> conv4
    for (int s = 0; s < 2; s++)
        gemm_plain_kernel<64, 8, 32, 4, 2>
            <<<dim3(BB * NN / 64, 1), dim3(4, 16)>>>(
                p_H3 + s * S3, w[s][3], p_Z + s * S4, H3, OUTD);
    for (int s = 0; s < 2; s++)
        gcn_layer_kernel<64, 8, 32, 4, 2, false, false>
            <<<dim3(8, 1, BB), dim3(4, 16)>>>(
                adj + (size_t)s * NN * NN, p_Z + s * S4, p_d + s * DH,
                bia[s][3], p_H4 + s * S4, OUTD);

    // 6) dynamic head params (uses conv3 = H3)
    dcl_params_kernel<<<NZ, 256>>>(task, wc, p_H3, p_WB);

    // 7) logits + interleave into cc
    cc_kernel<<<NZ, 256>>>(p_H4, p_WB, p_CC);

    // 8) final gram + softplus
    final_kernel<<<dim3(8, 8, NZ), dim3(16, 16)>>>(p_CC, out);

    (void)in_sizes; (void)n_in; (void)out_size;
}